// round 5
// baseline (speedup 1.0000x reference)
#include <cuda_runtime.h>
#include <cuda_fp16.h>
#include <cstdint>

// ---------------------------------------------------------------------------
// CrystalGraphConvolution via tensor cores (HMMA mma.sync m16n8k16).
//   P = x @ W_node  (fp16 in/out, fp32 accum)  [n_nodes, 512] interleaved (s,g)
//   Edge term E is NOT materialized: fused_edge computes the 64x256 E-tile
//   (eh @ W_edge + bias, fp32) in registers, stages to smem, then does the
//   per-edge gather + sigmoid*softplus + red.v4 segment-sum.
//   x = softplus(x + agg)
// ---------------------------------------------------------------------------

#define MAX_NODES 50000
#define MAX_EDGES 800000

static __device__ __align__(16) __half g_eh[(size_t)MAX_EDGES * 64];   // esph fp16
static __device__ __align__(16) __half g_P[(size_t)MAX_NODES * 512];
static __device__ __align__(16) __half g_xh[(size_t)MAX_NODES * 128];
static __device__ float g_agg[(size_t)MAX_NODES * 128];
static __device__ float g_x[(size_t)MAX_NODES * 128];
// B pre-swizzled into mma fragment order (uint = 2 halves {B[k][n], B[k+1][n]})
static __device__ __align__(16) unsigned g_Bn[8 * 64 * 64];   // node: K=128,N=512
static __device__ __align__(16) unsigned g_Be[4 * 32 * 64];   // edge: K=64, N=256
static __device__ float g_be[256];

__device__ __forceinline__ float fast_sigmoid(float x) {
    return __fdividef(1.0f, 1.0f + __expf(-x));
}
__device__ __forceinline__ float fast_softplus(float x) {
    return fmaxf(x, 0.0f) + __logf(1.0f + __expf(-fabsf(x)));
}

// ---------------------------------------------------------------------------
__device__ __forceinline__ float Bnode(const float* ks, const float* kg, int k, int j) {
    if (j < 256) { int c = j >> 1; return (j & 1) ? kg[k * 128 + c] : ks[k * 128 + c]; }
    int c = (j - 256) >> 1;
    return (j & 1) ? kg[(128 + k) * 128 + c] : ks[(128 + k) * 128 + c];
}
__device__ __forceinline__ float Bedge(const float* ks, const float* kg, int k, int j) {
    int c = j >> 1;
    return (j & 1) ? kg[(256 + k) * 128 + c] : ks[(256 + k) * 128 + c];
}
__device__ __forceinline__ unsigned pack2(float lo, float hi) {
    __half2 h = __floats2half2_rn(lo, hi);
    return *(unsigned*)&h;
}

// word(frag, w): frag = ks*NF + nf ; w in [0,64): lane = w>>1, j = w&1
//   k0 = ks*16 + (lane&3)*2 + j*8 ; n = nf*8 + (lane>>2); value={B[k0][n],B[k0+1][n]}
__global__ void repack_kernel(const float* __restrict__ ks, const float* __restrict__ kg,
                              const float* __restrict__ bs, const float* __restrict__ bg) {
    int i = blockIdx.x * blockDim.x + threadIdx.x;
    if (i < 8 * 64 * 64) {                       // node
        int w = i & 63, frag = i >> 6;
        int lane = w >> 1, j = w & 1;
        int kstep = frag / 64, nf = frag % 64;
        int k0 = kstep * 16 + (lane & 3) * 2 + j * 8;
        int n = nf * 8 + (lane >> 2);
        g_Bn[(size_t)frag * 64 + lane * 2 + j] =
            pack2(Bnode(ks, kg, k0, n), Bnode(ks, kg, k0 + 1, n));
    }
    if (i < 4 * 32 * 64) {                       // edge
        int w = i & 63, frag = i >> 6;
        int lane = w >> 1, j = w & 1;
        int kstep = frag / 32, nf = frag % 32;
        int k0 = kstep * 16 + (lane & 3) * 2 + j * 8;
        int n = nf * 8 + (lane >> 2);
        g_Be[(size_t)frag * 64 + lane * 2 + j] =
            pack2(Bedge(ks, kg, k0, n), Bedge(ks, kg, k0 + 1, n));
    }
    if (i < 256) {
        int c = i >> 1;
        g_be[i] = (i & 1) ? bg[c] : bs[c];
    }
}

// ---------------------------------------------------------------------------
// HMMA GEMM (node projection): C[M,N]=A[M,K]@B. 8 warps (2m x 4n), tile 64x256.
template<int N, int K>
__global__ __launch_bounds__(256) void hgemm(
    const __half* __restrict__ A, const unsigned* __restrict__ Bsw,
    __half* __restrict__ C, int M)
{
    constexpr int NF = N / 8;
    const int w = threadIdx.x >> 5, lane = threadIdx.x & 31;
    const int wm = w & 1, wn = w >> 1;
    const int m0 = blockIdx.y * 64 + wm * 32;
    const int n0 = blockIdx.x * 256 + wn * 64;
    const int g = lane >> 2, q2 = (lane & 3) * 2;
    const int nf0 = n0 >> 3;

    float acc[2][8][4];
#pragma unroll
    for (int i = 0; i < 2; i++)
#pragma unroll
        for (int f = 0; f < 8; f++)
#pragma unroll
            for (int t = 0; t < 4; t++) acc[i][f][t] = 0.0f;

#pragma unroll
    for (int ks = 0; ks < K / 16; ks++) {
        unsigned a[2][4];
#pragma unroll
        for (int i = 0; i < 2; i++) {
            int r = m0 + i * 16 + g;
            bool v0 = r < M, v1 = (r + 8) < M;
            const __half* p0 = A + (size_t)r * K + ks * 16 + q2;
            const __half* p1 = A + (size_t)(r + 8) * K + ks * 16 + q2;
            a[i][0] = v0 ? *(const unsigned*)p0 : 0u;
            a[i][1] = v1 ? *(const unsigned*)p1 : 0u;
            a[i][2] = v0 ? *(const unsigned*)(p0 + 8) : 0u;
            a[i][3] = v1 ? *(const unsigned*)(p1 + 8) : 0u;
        }
#pragma unroll
        for (int f = 0; f < 8; f++) {
            uint2 b = *(const uint2*)(Bsw + (size_t)(ks * NF + nf0 + f) * 64 + lane * 2);
#pragma unroll
            for (int i = 0; i < 2; i++) {
                asm volatile(
                    "mma.sync.aligned.m16n8k16.row.col.f32.f16.f16.f32 "
                    "{%0,%1,%2,%3}, {%4,%5,%6,%7}, {%8,%9}, {%0,%1,%2,%3};"
                    : "+f"(acc[i][f][0]), "+f"(acc[i][f][1]),
                      "+f"(acc[i][f][2]), "+f"(acc[i][f][3])
                    : "r"(a[i][0]), "r"(a[i][1]), "r"(a[i][2]), "r"(a[i][3]),
                      "r"(b.x), "r"(b.y));
            }
        }
    }

#pragma unroll
    for (int i = 0; i < 2; i++) {
        int r = m0 + i * 16 + g;
#pragma unroll
        for (int f = 0; f < 8; f++) {
            int n = n0 + f * 8 + q2;
            if (r < M) {
                __half2 h = __floats2half2_rn(acc[i][f][0], acc[i][f][1]);
                *(__half2*)(C + (size_t)r * N + n) = h;
            }
            if (r + 8 < M) {
                __half2 h = __floats2half2_rn(acc[i][f][2], acc[i][f][3]);
                *(__half2*)(C + (size_t)(r + 8) * N + n) = h;
            }
        }
    }
}

// ---------------------------------------------------------------------------
// Fused edge kernel. Block = 64 edges, 256 threads (8 warps).
// Phase 1: E-tile[64][256] = eh[e0:e0+64] @ We + bias  (HMMA, fp32) -> smem
// Phase 2: warp-per-edge (8 edges/warp): msg = sigmoid(s)*softplus(g),
//          red.global.add.v4.f32 into agg[src].
#define EPITCH 260   // floats per row (16B-aligned, bank-staggered)
__global__ __launch_bounds__(256, 2) void fused_edge(
    const __half* __restrict__ eh, const unsigned* __restrict__ Bsw,
    const float* __restrict__ bias, const __half* __restrict__ P,
    const int* __restrict__ pair, float* __restrict__ agg, int n_edges)
{
    extern __shared__ float sE[];   // [64][EPITCH]
    const int w = threadIdx.x >> 5, lane = threadIdx.x & 31;
    const int wm = w & 1, wn = w >> 1;
    const int e0 = blockIdx.x * 64;
    const int m0 = wm * 32;
    const int n0 = wn * 64;
    const int g = lane >> 2, q2 = (lane & 3) * 2;
    const int nf0 = n0 >> 3;

    // --- phase 1: MMA (K=64, NF=32), acc initialized with bias
    float acc[2][8][4];
#pragma unroll
    for (int f = 0; f < 8; f++) {
        float b0 = bias[n0 + f * 8 + q2];
        float b1 = bias[n0 + f * 8 + q2 + 1];
#pragma unroll
        for (int i = 0; i < 2; i++) {
            acc[i][f][0] = b0; acc[i][f][1] = b1;
            acc[i][f][2] = b0; acc[i][f][3] = b1;
        }
    }

#pragma unroll
    for (int ks = 0; ks < 4; ks++) {
        unsigned a[2][4];
#pragma unroll
        for (int i = 0; i < 2; i++) {
            int r = e0 + m0 + i * 16 + g;
            bool v0 = r < n_edges, v1 = (r + 8) < n_edges;
            const __half* p0 = eh + (size_t)r * 64 + ks * 16 + q2;
            const __half* p1 = eh + (size_t)(r + 8) * 64 + ks * 16 + q2;
            a[i][0] = v0 ? *(const unsigned*)p0 : 0u;
            a[i][1] = v1 ? *(const unsigned*)p1 : 0u;
            a[i][2] = v0 ? *(const unsigned*)(p0 + 8) : 0u;
            a[i][3] = v1 ? *(const unsigned*)(p1 + 8) : 0u;
        }
#pragma unroll
        for (int f = 0; f < 8; f++) {
            uint2 b = *(const uint2*)(Bsw + (size_t)(ks * 32 + nf0 + f) * 64 + lane * 2);
#pragma unroll
            for (int i = 0; i < 2; i++) {
                asm volatile(
                    "mma.sync.aligned.m16n8k16.row.col.f32.f16.f16.f32 "
                    "{%0,%1,%2,%3}, {%4,%5,%6,%7}, {%8,%9}, {%0,%1,%2,%3};"
                    : "+f"(acc[i][f][0]), "+f"(acc[i][f][1]),
                      "+f"(acc[i][f][2]), "+f"(acc[i][f][3])
                    : "r"(a[i][0]), "r"(a[i][1]), "r"(a[i][2]), "r"(a[i][3]),
                      "r"(b.x), "r"(b.y));
            }
        }
    }

    // stage E-tile to smem (fp32)
#pragma unroll
    for (int i = 0; i < 2; i++) {
        int r = m0 + i * 16 + g;
#pragma unroll
        for (int f = 0; f < 8; f++) {
            int n = n0 + f * 8 + q2;
            *(float2*)&sE[r * EPITCH + n] = make_float2(acc[i][f][0], acc[i][f][1]);
            *(float2*)&sE[(r + 8) * EPITCH + n] = make_float2(acc[i][f][2], acc[i][f][3]);
        }
    }
    __syncthreads();

    // --- phase 2: 8 edges per warp
#pragma unroll
    for (int t = 0; t < 8; t++) {
        int le = w * 8 + t;
        int e = e0 + le;
        if (e >= n_edges) break;
        int src = __ldg(&pair[2 * e]);
        int dst = __ldg(&pair[2 * e + 1]);

        uint4 a = *(const uint4*)(P + (size_t)src * 512 + lane * 8);
        uint4 b = *(const uint4*)(P + (size_t)dst * 512 + 256 + lane * 8);
        float4 ev0 = *(const float4*)&sE[le * EPITCH + lane * 8];
        float4 ev1 = *(const float4*)&sE[le * EPITCH + lane * 8 + 4];

        float m[4];
#pragma unroll
        for (int i = 0; i < 4; i++) {
            float2 fa = __half22float2(((const __half2*)&a)[i]);
            float2 fb = __half22float2(((const __half2*)&b)[i]);
            float es, eg;
            if (i == 0)      { es = ev0.x; eg = ev0.y; }
            else if (i == 1) { es = ev0.z; eg = ev0.w; }
            else if (i == 2) { es = ev1.x; eg = ev1.y; }
            else             { es = ev1.z; eg = ev1.w; }
            float s = fa.x + fb.x + es;
            float gg = fa.y + fb.y + eg;
            m[i] = fast_sigmoid(s) * fast_softplus(gg);
        }

        float* dp = agg + (size_t)src * 128 + lane * 4;
        asm volatile("red.global.add.v4.f32 [%0], {%1,%2,%3,%4};"
                     :: "l"(dp), "f"(m[0]), "f"(m[1]), "f"(m[2]), "f"(m[3])
                     : "memory");
    }
}

// ---------------------------------------------------------------------------
__global__ void zero_kernel(float4* __restrict__ p, int n4) {
    int i = blockIdx.x * blockDim.x + threadIdx.x;
    if (i < n4) p[i] = make_float4(0.f, 0.f, 0.f, 0.f);
}

__global__ void f2h_kernel(const float4* __restrict__ in, __half* __restrict__ out, int n4) {
    int i = blockIdx.x * blockDim.x + threadIdx.x;
    if (i < n4) {
        float4 v = in[i];
        __half2 h0 = __floats2half2_rn(v.x, v.y);
        __half2 h1 = __floats2half2_rn(v.z, v.w);
        *(uint2*)(out + (size_t)i * 4) = make_uint2(*(unsigned*)&h0, *(unsigned*)&h1);
    }
}

__global__ void update_kernel(const float* __restrict__ xin, const float* __restrict__ agg,
                              float* __restrict__ xout, __half* __restrict__ xh, int n) {
    int i = blockIdx.x * blockDim.x + threadIdx.x;
    if (i < n) {
        float v = fast_softplus(xin[i] + agg[i]);
        xout[i] = v;
        xh[i] = __float2half(v);
    }
}

// ---------------------------------------------------------------------------
extern "C" void kernel_launch(void* const* d_in, const int* in_sizes, int n_in,
                              void* d_out, int out_size) {
    const float* atom = (const float*)d_in[0];   // [n_nodes, 128]
    const float* esph = (const float*)d_in[1];   // [n_edges, 64]
    const float* ks   = (const float*)d_in[3];   // [320, 128]
    const float* bs   = (const float*)d_in[4];   // [128]
    const float* kg   = (const float*)d_in[5];   // [320, 128]
    const float* bg   = (const float*)d_in[6];   // [128]
    const int*   pair = (const int*)d_in[7];     // [n_edges, 2] int32
    float* out = (float*)d_out;

    const int n_nodes = in_sizes[0] / 128;
    const int n_edges = in_sizes[1] / 64;

    __half *pP, *pEh, *pXh;
    float *pAgg, *pX, *pBe;
    unsigned *pBn, *pBesw;
    cudaGetSymbolAddress((void**)&pP, g_P);
    cudaGetSymbolAddress((void**)&pEh, g_eh);
    cudaGetSymbolAddress((void**)&pXh, g_xh);
    cudaGetSymbolAddress((void**)&pAgg, g_agg);
    cudaGetSymbolAddress((void**)&pX, g_x);
    cudaGetSymbolAddress((void**)&pBn, g_Bn);
    cudaGetSymbolAddress((void**)&pBesw, g_Be);
    cudaGetSymbolAddress((void**)&pBe, g_be);

    const int fused_smem = 64 * EPITCH * 4;   // 66560 B
    cudaFuncSetAttribute(fused_edge, cudaFuncAttributeMaxDynamicSharedMemorySize,
                         fused_smem);

    // 1. repack weights into fragment-swizzled fp16
    repack_kernel<<<(8 * 64 * 64 + 255) / 256, 256>>>(ks, kg, bs, bg);

    // 2. convert esph -> fp16
    {
        int n4 = n_edges * 64 / 4;
        f2h_kernel<<<(n4 + 255) / 256, 256>>>((const float4*)esph, pEh, n4);
    }

    // 3. convert atom -> fp16 (step-0 GEMM input)
    {
        int n4 = n_nodes * 128 / 4;
        f2h_kernel<<<(n4 + 255) / 256, 256>>>((const float4*)atom, pXh, n4);
    }

    const float* xin = atom;
    const int nelem = n_nodes * 128;
    for (int step = 0; step < 3; step++) {
        zero_kernel<<<(nelem / 4 + 255) / 256, 256>>>((float4*)pAgg, nelem / 4);

        // P = x @ W_node (M=n_nodes, N=512, K=128) -> fp16
        dim3 gn(2, (n_nodes + 63) / 64);
        hgemm<512, 128><<<gn, 256>>>(pXh, pBn, pP, n_nodes);

        fused_edge<<<(n_edges + 63) / 64, 256, fused_smem>>>(
            pEh, pBesw, pBe, pP, pair, pAgg, n_edges);

        float* xout = (step == 2) ? out : pX;
        update_kernel<<<(nelem + 255) / 256, 256>>>(xin, pAgg, xout, pXh, nelem);
        xin = pX;
    }
}

// round 6
// speedup vs baseline: 1.3741x; 1.3741x over previous
#include <cuda_runtime.h>
#include <cuda_fp16.h>
#include <cstdint>

// ---------------------------------------------------------------------------
// CrystalGraphConvolution (tensor-core HMMA + CSR aggregation).
//   E = esph @ W_edge + bias  (once, fp16, interleaved (s,g))    [n_edges,256]
//   per step:
//     P = x @ W_node          (fp16, interleaved (s,g))          [n_nodes,512]
//     node_gather: warp/node walks CSR edge list, msg = sigmoid(s)*softplus(g)
//                  accumulated in registers; x' = softplus(x + agg) fused.
// CSR (row_ptr/perm over src) built once per launch on device.
// ---------------------------------------------------------------------------

#define MAX_NODES 50000
#define MAX_EDGES 800000

static __device__ __align__(16) __half g_E[(size_t)MAX_EDGES * 256];   // ~410 MB
static __device__ __align__(16) __half g_eh[(size_t)MAX_EDGES * 64];
static __device__ __align__(16) __half g_P[(size_t)MAX_NODES * 512];
static __device__ __align__(16) __half g_xh[(size_t)MAX_NODES * 128];
static __device__ float g_x[(size_t)MAX_NODES * 128];
static __device__ __align__(16) unsigned g_Bn[8 * 64 * 64];   // node B swizzled
static __device__ __align__(16) unsigned g_Be[4 * 32 * 64];   // edge B swizzled
static __device__ float g_be[256];
// CSR scratch
static __device__ int g_cnt[MAX_NODES];
static __device__ int g_rowptr[MAX_NODES + 1];
static __device__ int g_cursor[MAX_NODES];
static __device__ int g_perm[MAX_EDGES];

__device__ __forceinline__ float fast_sigmoid(float x) {
    return __fdividef(1.0f, 1.0f + __expf(-x));
}
__device__ __forceinline__ float fast_softplus(float x) {
    return fmaxf(x, 0.0f) + __logf(1.0f + __expf(-fabsf(x)));
}

// ---------------------------------------------------------------------------
__device__ __forceinline__ float Bnode(const float* ks, const float* kg, int k, int j) {
    if (j < 256) { int c = j >> 1; return (j & 1) ? kg[k * 128 + c] : ks[k * 128 + c]; }
    int c = (j - 256) >> 1;
    return (j & 1) ? kg[(128 + k) * 128 + c] : ks[(128 + k) * 128 + c];
}
__device__ __forceinline__ float Bedge(const float* ks, const float* kg, int k, int j) {
    int c = j >> 1;
    return (j & 1) ? kg[(256 + k) * 128 + c] : ks[(256 + k) * 128 + c];
}
__device__ __forceinline__ unsigned pack2(float lo, float hi) {
    __half2 h = __floats2half2_rn(lo, hi);
    return *(unsigned*)&h;
}

// word(frag, w): frag = ks*NF + nf ; w in [0,64): lane = w>>1, j = w&1
//   k0 = ks*16 + (lane&3)*2 + j*8 ; n = nf*8 + (lane>>2); value={B[k0][n],B[k0+1][n]}
__global__ void repack_kernel(const float* __restrict__ ks, const float* __restrict__ kg,
                              const float* __restrict__ bs, const float* __restrict__ bg) {
    int i = blockIdx.x * blockDim.x + threadIdx.x;
    if (i < 8 * 64 * 64) {                       // node
        int w = i & 63, frag = i >> 6;
        int lane = w >> 1, j = w & 1;
        int kstep = frag / 64, nf = frag % 64;
        int k0 = kstep * 16 + (lane & 3) * 2 + j * 8;
        int n = nf * 8 + (lane >> 2);
        g_Bn[(size_t)frag * 64 + lane * 2 + j] =
            pack2(Bnode(ks, kg, k0, n), Bnode(ks, kg, k0 + 1, n));
    }
    if (i < 4 * 32 * 64) {                       // edge
        int w = i & 63, frag = i >> 6;
        int lane = w >> 1, j = w & 1;
        int kstep = frag / 32, nf = frag % 32;
        int k0 = kstep * 16 + (lane & 3) * 2 + j * 8;
        int n = nf * 8 + (lane >> 2);
        g_Be[(size_t)frag * 64 + lane * 2 + j] =
            pack2(Bedge(ks, kg, k0, n), Bedge(ks, kg, k0 + 1, n));
    }
    if (i < 256) {
        int c = i >> 1;
        g_be[i] = (i & 1) ? bg[c] : bs[c];
    }
}

// ---------------------------------------------------------------------------
// HMMA GEMM: C[M,N]=A[M,K]@B(+bias). 8 warps (2m x 4n), tile 64x256.
// Epilogue staged through smem for fully coalesced 16B/lane global stores.
template<int N, int K>
__global__ __launch_bounds__(256) void hgemm(
    const __half* __restrict__ A, const unsigned* __restrict__ Bsw,
    const float* __restrict__ bias, __half* __restrict__ C, int M)
{
    __shared__ __half sC[64][264];   // 264 = 256 + 8 pad (conflict-free STS)
    constexpr int NF = N / 8;
    const int w = threadIdx.x >> 5, lane = threadIdx.x & 31;
    const int wm = w & 1, wn = w >> 1;
    const int m0 = blockIdx.y * 64 + wm * 32;
    const int n0 = blockIdx.x * 256 + wn * 64;
    const int g = lane >> 2, q2 = (lane & 3) * 2;
    const int nf0 = n0 >> 3;

    float acc[2][8][4];
#pragma unroll
    for (int i = 0; i < 2; i++)
#pragma unroll
        for (int f = 0; f < 8; f++)
#pragma unroll
            for (int t = 0; t < 4; t++) acc[i][f][t] = 0.0f;

#pragma unroll
    for (int ks = 0; ks < K / 16; ks++) {
        unsigned a[2][4];
#pragma unroll
        for (int i = 0; i < 2; i++) {
            int r = m0 + i * 16 + g;
            bool v0 = r < M, v1 = (r + 8) < M;
            const __half* p0 = A + (size_t)r * K + ks * 16 + q2;
            const __half* p1 = A + (size_t)(r + 8) * K + ks * 16 + q2;
            a[i][0] = v0 ? *(const unsigned*)p0 : 0u;
            a[i][1] = v1 ? *(const unsigned*)p1 : 0u;
            a[i][2] = v0 ? *(const unsigned*)(p0 + 8) : 0u;
            a[i][3] = v1 ? *(const unsigned*)(p1 + 8) : 0u;
        }
#pragma unroll
        for (int f = 0; f < 8; f++) {
            uint2 b = *(const uint2*)(Bsw + (size_t)(ks * NF + nf0 + f) * 64 + lane * 2);
#pragma unroll
            for (int i = 0; i < 2; i++) {
                asm volatile(
                    "mma.sync.aligned.m16n8k16.row.col.f32.f16.f16.f32 "
                    "{%0,%1,%2,%3}, {%4,%5,%6,%7}, {%8,%9}, {%0,%1,%2,%3};"
                    : "+f"(acc[i][f][0]), "+f"(acc[i][f][1]),
                      "+f"(acc[i][f][2]), "+f"(acc[i][f][3])
                    : "r"(a[i][0]), "r"(a[i][1]), "r"(a[i][2]), "r"(a[i][3]),
                      "r"(b.x), "r"(b.y));
            }
        }
    }

    // epilogue: acc (+bias) -> smem
#pragma unroll
    for (int i = 0; i < 2; i++) {
        int rl = wm * 32 + i * 16 + g;       // local row in [0,64)
#pragma unroll
        for (int f = 0; f < 8; f++) {
            int nl = wn * 64 + f * 8 + q2;   // local col in [0,256)
            float b0 = 0.f, b1 = 0.f;
            if (bias) { b0 = bias[blockIdx.x * 256 + nl]; b1 = bias[blockIdx.x * 256 + nl + 1]; }
            *(__half2*)&sC[rl][nl]     = __floats2half2_rn(acc[i][f][0] + b0, acc[i][f][1] + b1);
            *(__half2*)&sC[rl + 8][nl] = __floats2half2_rn(acc[i][f][2] + b0, acc[i][f][3] + b1);
        }
    }
    __syncthreads();

    // coalesced copy: warp w copies rows w*8 .. w*8+7 (512B contiguous each)
#pragma unroll
    for (int rr = 0; rr < 8; rr++) {
        int rl = w * 8 + rr;
        int grow = blockIdx.y * 64 + rl;
        if (grow < M)
            *(uint4*)(C + (size_t)grow * N + blockIdx.x * 256 + lane * 8) =
                *(uint4*)&sC[rl][lane * 8];
    }
}

// ---------------------------------------------------------------------------
// CSR build
__global__ void zero_int(int* __restrict__ p, int n) {
    int i = blockIdx.x * blockDim.x + threadIdx.x;
    if (i < n) p[i] = 0;
}
__global__ void hist_kernel(const int* __restrict__ pair, int* __restrict__ cnt, int n_edges) {
    int e = blockIdx.x * blockDim.x + threadIdx.x;
    if (e < n_edges) atomicAdd(&cnt[pair[2 * e]], 1);
}
__global__ void scan_kernel(const int* __restrict__ cnt, int* __restrict__ rowptr,
                            int* __restrict__ cursor, int n_nodes) {
    __shared__ int tot[1024];
    const int t = threadIdx.x;
    const int C = (n_nodes + 1023) / 1024;
    const int base = t * C;
    int s = 0;
    for (int k = 0; k < C; k++) {
        int i = base + k;
        if (i < n_nodes) s += cnt[i];
    }
    tot[t] = s;
    __syncthreads();
    for (int off = 1; off < 1024; off <<= 1) {
        int val = (t >= off) ? tot[t - off] : 0;
        __syncthreads();
        tot[t] += val;
        __syncthreads();
    }
    s = (t > 0) ? tot[t - 1] : 0;
    for (int k = 0; k < C; k++) {
        int i = base + k;
        if (i < n_nodes) {
            rowptr[i] = s;
            cursor[i] = s;
            s += cnt[i];
        }
    }
    if (t == 1023) rowptr[n_nodes] = tot[1023];
}
__global__ void scatter_kernel(const int* __restrict__ pair, int* __restrict__ cursor,
                               int* __restrict__ perm, int n_edges) {
    int e = blockIdx.x * blockDim.x + threadIdx.x;
    if (e < n_edges) {
        int pos = atomicAdd(&cursor[pair[2 * e]], 1);
        perm[pos] = e;
    }
}

// ---------------------------------------------------------------------------
// Warp per node: walk CSR edge list, accumulate messages in regs, fused update.
__global__ __launch_bounds__(256) void node_gather(
    const __half* __restrict__ P, const __half* __restrict__ E,
    const int* __restrict__ pair, const int* __restrict__ rowptr,
    const int* __restrict__ perm,
    const float* __restrict__ xin, float* __restrict__ xout,
    __half* __restrict__ xh, int n_nodes)
{
    int v = (blockIdx.x * blockDim.x + threadIdx.x) >> 5;
    int lane = threadIdx.x & 31;
    if (v >= n_nodes) return;

    const int beg = rowptr[v];
    const int end = rowptr[v + 1];

    // src-side projection: loop-invariant, load once
    uint4 a = *(const uint4*)(P + (size_t)v * 512 + lane * 8);
    float2 fa[4];
#pragma unroll
    for (int i = 0; i < 4; i++) fa[i] = __half22float2(((const __half2*)&a)[i]);

    float acc[4] = {0.f, 0.f, 0.f, 0.f};

    int e = 0, dst = 0;
    if (beg < end) { e = __ldg(&perm[beg]); dst = __ldg(&pair[2 * e + 1]); }
    for (int j = beg; j < end; j++) {
        int ec = e, dc = dst;
        if (j + 1 < end) { e = __ldg(&perm[j + 1]); dst = __ldg(&pair[2 * e + 1]); }

        uint4 b  = *(const uint4*)(P + (size_t)dc * 512 + 256 + lane * 8);
        uint4 ev = *(const uint4*)(E + (size_t)ec * 256 + lane * 8);
#pragma unroll
        for (int i = 0; i < 4; i++) {
            float2 fb = __half22float2(((const __half2*)&b)[i]);
            float2 fe = __half22float2(((const __half2*)&ev)[i]);
            float s  = fa[i].x + fb.x + fe.x;
            float gg = fa[i].y + fb.y + fe.y;
            acc[i] += fast_sigmoid(s) * fast_softplus(gg);
        }
    }

    float4 xv = *(const float4*)(xin + (size_t)v * 128 + lane * 4);
    float4 o;
    o.x = fast_softplus(xv.x + acc[0]);
    o.y = fast_softplus(xv.y + acc[1]);
    o.z = fast_softplus(xv.z + acc[2]);
    o.w = fast_softplus(xv.w + acc[3]);
    *(float4*)(xout + (size_t)v * 128 + lane * 4) = o;
    __half2 h0 = __floats2half2_rn(o.x, o.y);
    __half2 h1 = __floats2half2_rn(o.z, o.w);
    *(uint2*)(xh + (size_t)v * 128 + lane * 4) = make_uint2(*(unsigned*)&h0, *(unsigned*)&h1);
}

// ---------------------------------------------------------------------------
__global__ void f2h_kernel(const float4* __restrict__ in, __half* __restrict__ out, int n4) {
    int i = blockIdx.x * blockDim.x + threadIdx.x;
    if (i < n4) {
        float4 v = in[i];
        __half2 h0 = __floats2half2_rn(v.x, v.y);
        __half2 h1 = __floats2half2_rn(v.z, v.w);
        *(uint2*)(out + (size_t)i * 4) = make_uint2(*(unsigned*)&h0, *(unsigned*)&h1);
    }
}

// ---------------------------------------------------------------------------
extern "C" void kernel_launch(void* const* d_in, const int* in_sizes, int n_in,
                              void* d_out, int out_size) {
    const float* atom = (const float*)d_in[0];   // [n_nodes, 128]
    const float* esph = (const float*)d_in[1];   // [n_edges, 64]
    const float* ks   = (const float*)d_in[3];   // [320, 128]
    const float* bs   = (const float*)d_in[4];   // [128]
    const float* kg   = (const float*)d_in[5];   // [320, 128]
    const float* bg   = (const float*)d_in[6];   // [128]
    const int*   pair = (const int*)d_in[7];     // [n_edges, 2] int32
    float* out = (float*)d_out;

    const int n_nodes = in_sizes[0] / 128;
    const int n_edges = in_sizes[1] / 64;

    __half *pE, *pP, *pEh, *pXh;
    float *pX, *pBe;
    unsigned *pBn, *pBesw;
    int *pCnt, *pRow, *pCur, *pPerm;
    cudaGetSymbolAddress((void**)&pE, g_E);
    cudaGetSymbolAddress((void**)&pP, g_P);
    cudaGetSymbolAddress((void**)&pEh, g_eh);
    cudaGetSymbolAddress((void**)&pXh, g_xh);
    cudaGetSymbolAddress((void**)&pX, g_x);
    cudaGetSymbolAddress((void**)&pBn, g_Bn);
    cudaGetSymbolAddress((void**)&pBesw, g_Be);
    cudaGetSymbolAddress((void**)&pBe, g_be);
    cudaGetSymbolAddress((void**)&pCnt, g_cnt);
    cudaGetSymbolAddress((void**)&pRow, g_rowptr);
    cudaGetSymbolAddress((void**)&pCur, g_cursor);
    cudaGetSymbolAddress((void**)&pPerm, g_perm);

    // --- CSR build (graph static across steps)
    zero_int<<<(n_nodes + 255) / 256, 256>>>(pCnt, n_nodes);
    hist_kernel<<<(n_edges + 255) / 256, 256>>>(pair, pCnt, n_edges);
    scan_kernel<<<1, 1024>>>(pCnt, pRow, pCur, n_nodes);
    scatter_kernel<<<(n_edges + 255) / 256, 256>>>(pair, pCur, pPerm, n_edges);

    // --- weights + fp16 inputs
    repack_kernel<<<(8 * 64 * 64 + 255) / 256, 256>>>(ks, kg, bs, bg);
    {
        int n4 = n_edges * 64 / 4;
        f2h_kernel<<<(n4 + 255) / 256, 256>>>((const float4*)esph, pEh, n4);
    }
    {
        int n4 = n_nodes * 128 / 4;
        f2h_kernel<<<(n4 + 255) / 256, 256>>>((const float4*)atom, pXh, n4);
    }

    // --- E = esph @ W_edge + bias (once)
    {
        dim3 grid(1, (n_edges + 63) / 64);
        hgemm<256, 64><<<grid, 256>>>(pEh, pBesw, pBe, pE, n_edges);
    }

    const float* xin = atom;
    for (int step = 0; step < 3; step++) {
        // P = x @ W_node
        dim3 gn(2, (n_nodes + 63) / 64);
        hgemm<512, 128><<<gn, 256>>>(pXh, pBn, nullptr, pP, n_nodes);

        float* xout = (step == 2) ? out : pX;
        node_gather<<<(n_nodes * 32 + 255) / 256, 256>>>(
            pP, pE, pair, pRow, pPerm, xin, xout, pXh, n_nodes);
        xin = pX;
    }
}